// round 2
// baseline (speedup 1.0000x reference)
#include <cuda_runtime.h>

// Problem constants
#define B_  16
#define D_  1024
#define L_  512
#define T_  2048
#define LN_EPS 1e-5f

// ---------------------------------------------------------------------------
// Scratch (device globals; no allocations allowed).  448 MB total.
// g_theta is reused for t_x after the scores GEMM consumes theta.
// ---------------------------------------------------------------------------
__device__ float g_theta[(size_t)B_ * L_ * T_];   //  64 MB  [b][l][t]  (later: t_x)
__device__ float g_phi  [(size_t)B_ * L_ * T_];   //  64 MB  [b][l][t]
__device__ float g_g    [(size_t)B_ * L_ * T_];   //  64 MB  [b][l][t]
__device__ float g_S    [(size_t)B_ * T_ * T_];   // 256 MB  [b][t][s]
__device__ float g_part [B_ * 64 * 2];
__device__ float g_stats[B_ * 2];                 // per-batch {mean, rstd}

// ---------------------------------------------------------------------------
// Shared 16-deep 128x128 microkernel. PA/PB are smem row pitches (pad = 132
// where the tile was written via scalar transpose-scatter).
// ---------------------------------------------------------------------------
template<int PA, int PB>
__device__ __forceinline__ void mm16(const float* As, const float* Bs,
                                     float (&acc)[8][8], int ty, int tx)
{
#pragma unroll
    for (int k = 0; k < 16; ++k) {
        float ra[8], rb[8];
        *(float4*)(ra)     = *(const float4*)(As + k * PA + ty * 8);
        *(float4*)(ra + 4) = *(const float4*)(As + k * PA + ty * 8 + 4);
        *(float4*)(rb)     = *(const float4*)(Bs + k * PB + tx * 8);
        *(float4*)(rb + 4) = *(const float4*)(Bs + k * PB + tx * 8 + 4);
#pragma unroll
        for (int i = 0; i < 8; ++i)
#pragma unroll
            for (int j = 0; j < 8; ++j)
                acc[i][j] = fmaf(ra[i], rb[j], acc[i][j]);
    }
}

// ---------------------------------------------------------------------------
// K1: projection.  C[b][l,t] = sum_d W[l,d] * X[b][d,t] + bias[l]
// M=512 (l), N=2048 (t), K=1024 (d).  which: 0=theta, 1=phi, 2=g
// grid (T/128=16, L/128=4, B), block 256
// ---------------------------------------------------------------------------
__global__ __launch_bounds__(256)
void proj_kernel(const float* __restrict__ W, const float* __restrict__ bias,
                 const float* __restrict__ X, int which)
{
    __shared__ float As[16 * 132];
    __shared__ float Bs[16 * 128];

    float* C = (which == 0) ? g_theta : (which == 1) ? g_phi : g_g;
    const int b  = blockIdx.z;
    const int m0 = blockIdx.y * 128;
    const int n0 = blockIdx.x * 128;
    const int t  = threadIdx.x;

    const float* Xb = X + (size_t)b * D_ * T_;
    float*       Cb = C + (size_t)b * L_ * T_;

    const int ty = t >> 4, tx = t & 15;
    const int aRow = t >> 2,  aCol = (t & 3) * 4;     // A transpose-load
    const int bRow = t >> 5,  bCol = (t & 31) * 4;    // B direct load

    float acc[8][8] = {};

    for (int k0 = 0; k0 < D_; k0 += 16) {
        float4 a0 = *(const float4*)(W  + (size_t)(m0 + aRow)      * D_ + k0 + aCol);
        float4 a1 = *(const float4*)(W  + (size_t)(m0 + aRow + 64) * D_ + k0 + aCol);
        float4 b0 = *(const float4*)(Xb + (size_t)(k0 + bRow)      * T_ + n0 + bCol);
        float4 b1 = *(const float4*)(Xb + (size_t)(k0 + bRow + 8)  * T_ + n0 + bCol);
        __syncthreads();
        As[(aCol + 0) * 132 + aRow]      = a0.x;
        As[(aCol + 1) * 132 + aRow]      = a0.y;
        As[(aCol + 2) * 132 + aRow]      = a0.z;
        As[(aCol + 3) * 132 + aRow]      = a0.w;
        As[(aCol + 0) * 132 + aRow + 64] = a1.x;
        As[(aCol + 1) * 132 + aRow + 64] = a1.y;
        As[(aCol + 2) * 132 + aRow + 64] = a1.z;
        As[(aCol + 3) * 132 + aRow + 64] = a1.w;
        *(float4*)(Bs + bRow * 128 + bCol)       = b0;
        *(float4*)(Bs + (bRow + 8) * 128 + bCol) = b1;
        __syncthreads();
        mm16<132, 128>(As, Bs, acc, ty, tx);
    }

#pragma unroll
    for (int i = 0; i < 8; ++i) {
        const int   m  = m0 + ty * 8 + i;
        const float bi = bias[m];
        float* cp = Cb + (size_t)m * T_ + n0 + tx * 8;
        float4 c0 = make_float4(acc[i][0] + bi, acc[i][1] + bi, acc[i][2] + bi, acc[i][3] + bi);
        float4 c1 = make_float4(acc[i][4] + bi, acc[i][5] + bi, acc[i][6] + bi, acc[i][7] + bi);
        *(float4*)(cp)     = c0;
        *(float4*)(cp + 4) = c1;
    }
}

// ---------------------------------------------------------------------------
// K2: scores.  S[b][t,s] = sum_l theta[b][l,t] * phi[b][l,s]
// M=2048 (t), N=2048 (s), K=512 (l). Both operands k-row-major -> direct loads.
// grid (16, 16, B), block 256
// ---------------------------------------------------------------------------
__global__ __launch_bounds__(256)
void scores_kernel()
{
    __shared__ float As[16 * 128];
    __shared__ float Bs[16 * 128];

    const int b  = blockIdx.z;
    const int m0 = blockIdx.y * 128;
    const int n0 = blockIdx.x * 128;
    const int t  = threadIdx.x;

    const float* TH = g_theta + (size_t)b * L_ * T_;
    const float* PH = g_phi   + (size_t)b * L_ * T_;
    float*       Sb = g_S     + (size_t)b * T_ * T_;

    const int ty = t >> 4, tx = t & 15;
    const int r = t >> 5, c4 = (t & 31) * 4;

    float acc[8][8] = {};

    for (int k0 = 0; k0 < L_; k0 += 16) {
        float4 a0 = *(const float4*)(TH + (size_t)(k0 + r)     * T_ + m0 + c4);
        float4 a1 = *(const float4*)(TH + (size_t)(k0 + r + 8) * T_ + m0 + c4);
        float4 b0 = *(const float4*)(PH + (size_t)(k0 + r)     * T_ + n0 + c4);
        float4 b1 = *(const float4*)(PH + (size_t)(k0 + r + 8) * T_ + n0 + c4);
        __syncthreads();
        *(float4*)(As + r * 128 + c4)       = a0;
        *(float4*)(As + (r + 8) * 128 + c4) = a1;
        *(float4*)(Bs + r * 128 + c4)       = b0;
        *(float4*)(Bs + (r + 8) * 128 + c4) = b1;
        __syncthreads();
        mm16<128, 128>(As, Bs, acc, ty, tx);
    }

#pragma unroll
    for (int i = 0; i < 8; ++i) {
        float* cp = Sb + (size_t)(m0 + ty * 8 + i) * T_ + n0 + tx * 8;
        *(float4*)(cp)     = make_float4(acc[i][0], acc[i][1], acc[i][2], acc[i][3]);
        *(float4*)(cp + 4) = make_float4(acc[i][4], acc[i][5], acc[i][6], acc[i][7]);
    }
}

// ---------------------------------------------------------------------------
// K3: in-place row softmax over s.  One block per row (B*T rows of length T).
// ---------------------------------------------------------------------------
__global__ __launch_bounds__(256)
void softmax_kernel()
{
    __shared__ float red[8];
    const size_t row = blockIdx.x;
    float* r = g_S + row * T_;
    const int t = threadIdx.x;

    float4 v0 = ((const float4*)r)[t];
    float4 v1 = ((const float4*)r)[t + 256];

    float m = fmaxf(fmaxf(fmaxf(v0.x, v0.y), fmaxf(v0.z, v0.w)),
                    fmaxf(fmaxf(v1.x, v1.y), fmaxf(v1.z, v1.w)));
#pragma unroll
    for (int o = 16; o; o >>= 1) m = fmaxf(m, __shfl_xor_sync(0xffffffffu, m, o));
    if ((t & 31) == 0) red[t >> 5] = m;
    __syncthreads();
    m = fmaxf(fmaxf(fmaxf(red[0], red[1]), fmaxf(red[2], red[3])),
              fmaxf(fmaxf(red[4], red[5]), fmaxf(red[6], red[7])));
    __syncthreads();

    v0.x = __expf(v0.x - m); v0.y = __expf(v0.y - m);
    v0.z = __expf(v0.z - m); v0.w = __expf(v0.w - m);
    v1.x = __expf(v1.x - m); v1.y = __expf(v1.y - m);
    v1.z = __expf(v1.z - m); v1.w = __expf(v1.w - m);

    float s = (v0.x + v0.y) + (v0.z + v0.w) + (v1.x + v1.y) + (v1.z + v1.w);
#pragma unroll
    for (int o = 16; o; o >>= 1) s += __shfl_xor_sync(0xffffffffu, s, o);
    if ((t & 31) == 0) red[t >> 5] = s;
    __syncthreads();
    s = (red[0] + red[1]) + (red[2] + red[3]) + (red[4] + red[5]) + (red[6] + red[7]);

    const float inv = 1.0f / s;
    v0.x *= inv; v0.y *= inv; v0.z *= inv; v0.w *= inv;
    v1.x *= inv; v1.y *= inv; v1.z *= inv; v1.w *= inv;
    ((float4*)r)[t]       = v0;
    ((float4*)r)[t + 256] = v1;
}

// ---------------------------------------------------------------------------
// K4: attention apply.  tx[b][l,t] = sum_s g[b][l,s] * P[b][t,s]
// Writes into g_theta (theta is dead after K2).
// M=512 (l), N=2048 (t), K=2048 (s). Both operands need transpose-loads.
// grid (16, 4, B), block 256
// ---------------------------------------------------------------------------
__global__ __launch_bounds__(256)
void attn_kernel()
{
    __shared__ float As[16 * 132];
    __shared__ float Bs[16 * 132];

    const int b  = blockIdx.z;
    const int m0 = blockIdx.y * 128;
    const int n0 = blockIdx.x * 128;
    const int t  = threadIdx.x;

    const float* G = g_g     + (size_t)b * L_ * T_;
    const float* P = g_S     + (size_t)b * T_ * T_;
    float*       C = g_theta + (size_t)b * L_ * T_;   // reuse theta as t_x

    const int ty = t >> 4, tx = t & 15;
    const int aRow = t >> 2, aCol = (t & 3) * 4;

    float acc[8][8] = {};

    for (int k0 = 0; k0 < T_; k0 += 16) {
        float4 a0 = *(const float4*)(G + (size_t)(m0 + aRow)      * T_ + k0 + aCol);
        float4 a1 = *(const float4*)(G + (size_t)(m0 + aRow + 64) * T_ + k0 + aCol);
        float4 p0 = *(const float4*)(P + (size_t)(n0 + aRow)      * T_ + k0 + aCol);
        float4 p1 = *(const float4*)(P + (size_t)(n0 + aRow + 64) * T_ + k0 + aCol);
        __syncthreads();
        As[(aCol + 0) * 132 + aRow]      = a0.x;
        As[(aCol + 1) * 132 + aRow]      = a0.y;
        As[(aCol + 2) * 132 + aRow]      = a0.z;
        As[(aCol + 3) * 132 + aRow]      = a0.w;
        As[(aCol + 0) * 132 + aRow + 64] = a1.x;
        As[(aCol + 1) * 132 + aRow + 64] = a1.y;
        As[(aCol + 2) * 132 + aRow + 64] = a1.z;
        As[(aCol + 3) * 132 + aRow + 64] = a1.w;
        Bs[(aCol + 0) * 132 + aRow]      = p0.x;
        Bs[(aCol + 1) * 132 + aRow]      = p0.y;
        Bs[(aCol + 2) * 132 + aRow]      = p0.z;
        Bs[(aCol + 3) * 132 + aRow]      = p0.w;
        Bs[(aCol + 0) * 132 + aRow + 64] = p1.x;
        Bs[(aCol + 1) * 132 + aRow + 64] = p1.y;
        Bs[(aCol + 2) * 132 + aRow + 64] = p1.z;
        Bs[(aCol + 3) * 132 + aRow + 64] = p1.w;
        __syncthreads();
        mm16<132, 132>(As, Bs, acc, ty, tx);
    }

#pragma unroll
    for (int i = 0; i < 8; ++i) {
        float* cp = C + (size_t)(m0 + ty * 8 + i) * T_ + n0 + tx * 8;
        *(float4*)(cp)     = make_float4(acc[i][0], acc[i][1], acc[i][2], acc[i][3]);
        *(float4*)(cp + 4) = make_float4(acc[i][4], acc[i][5], acc[i][6], acc[i][7]);
    }
}

// ---------------------------------------------------------------------------
// K5a/K5b: deterministic two-stage LayerNorm statistics over t_x[b] (L*T elems)
// ---------------------------------------------------------------------------
__global__ __launch_bounds__(256)
void reduce1_kernel()
{
    __shared__ float rs[8], rq[8];
    const int b = blockIdx.y, c = blockIdx.x;
    const float4* base = (const float4*)(g_theta + (size_t)b * L_ * T_
                                                 + (size_t)c * (L_ * T_ / 64));
    float s = 0.f, q = 0.f;
    for (int i = threadIdx.x; i < (L_ * T_ / 64) / 4; i += 256) {
        float4 v = base[i];
        s += (v.x + v.y) + (v.z + v.w);
        q += (v.x * v.x + v.y * v.y) + (v.z * v.z + v.w * v.w);
    }
#pragma unroll
    for (int o = 16; o; o >>= 1) {
        s += __shfl_xor_sync(0xffffffffu, s, o);
        q += __shfl_xor_sync(0xffffffffu, q, o);
    }
    const int t = threadIdx.x;
    if ((t & 31) == 0) { rs[t >> 5] = s; rq[t >> 5] = q; }
    __syncthreads();
    if (t == 0) {
        float S = 0.f, Q = 0.f;
#pragma unroll
        for (int i = 0; i < 8; ++i) { S += rs[i]; Q += rq[i]; }
        g_part[(b * 64 + c) * 2]     = S;
        g_part[(b * 64 + c) * 2 + 1] = Q;
    }
}

__global__ __launch_bounds__(64)
void reduce2_kernel()
{
    __shared__ float rs[2], rq[2];
    const int b = blockIdx.x, t = threadIdx.x;
    float s = g_part[(b * 64 + t) * 2];
    float q = g_part[(b * 64 + t) * 2 + 1];
#pragma unroll
    for (int o = 16; o; o >>= 1) {
        s += __shfl_xor_sync(0xffffffffu, s, o);
        q += __shfl_xor_sync(0xffffffffu, q, o);
    }
    if ((t & 31) == 0) { rs[t >> 5] = s; rq[t >> 5] = q; }
    __syncthreads();
    if (t == 0) {
        const float n    = (float)((size_t)L_ * T_);
        const float S    = rs[0] + rs[1];
        const float Q    = rq[0] + rq[1];
        const float mean = S / n;
        const float var  = Q / n - mean * mean;
        g_stats[b * 2]     = mean;
        g_stats[b * 2 + 1] = 1.0f / sqrtf(var + LN_EPS);
    }
}

// ---------------------------------------------------------------------------
// K6: output.  out[b][o,t] = sum_l Wo[o,l]*relu((tx[b][l,t]-mu)*rstd*gamma[l,t]
//                                               + beta[l,t]) + bo[o] + in2[b][o,t]
// M=1024 (o), N=2048 (t), K=512 (l).  grid (16, 8, B), block 256
// ---------------------------------------------------------------------------
__global__ __launch_bounds__(256)
void out_kernel(const float* __restrict__ Wo, const float* __restrict__ bo,
                const float* __restrict__ gamma, const float* __restrict__ beta,
                const float* __restrict__ in2, float* __restrict__ Out)
{
    __shared__ float As[16 * 132];
    __shared__ float Bs[16 * 128];

    const int b  = blockIdx.z;
    const int m0 = blockIdx.y * 128;
    const int n0 = blockIdx.x * 128;
    const int t  = threadIdx.x;

    const float* TX   = g_theta + (size_t)b * L_ * T_;   // t_x lives in g_theta
    const float  mu   = g_stats[b * 2];
    const float  rstd = g_stats[b * 2 + 1];

    const int ty = t >> 4, tx = t & 15;
    const int aRow = t >> 2,  aCol = (t & 3) * 4;
    const int bRow = t >> 5,  bCol = (t & 31) * 4;

    float acc[8][8] = {};

    for (int k0 = 0; k0 < L_; k0 += 16) {
        float4 a0 = *(const float4*)(Wo + (size_t)(m0 + aRow)      * L_ + k0 + aCol);
        float4 a1 = *(const float4*)(Wo + (size_t)(m0 + aRow + 64) * L_ + k0 + aCol);

        const size_t o0 = (size_t)(k0 + bRow)     * T_ + n0 + bCol;
        const size_t o1 = (size_t)(k0 + bRow + 8) * T_ + n0 + bCol;
        float4 x0 = *(const float4*)(TX + o0);
        float4 x1 = *(const float4*)(TX + o1);
        float4 g0 = *(const float4*)(gamma + o0);
        float4 g1 = *(const float4*)(gamma + o1);
        float4 e0 = *(const float4*)(beta + o0);
        float4 e1 = *(const float4*)(beta + o1);

        float4 h0, h1;
        h0.x = fmaxf(0.f, (x0.x - mu) * rstd * g0.x + e0.x);
        h0.y = fmaxf(0.f, (x0.y - mu) * rstd * g0.y + e0.y);
        h0.z = fmaxf(0.f, (x0.z - mu) * rstd * g0.z + e0.z);
        h0.w = fmaxf(0.f, (x0.w - mu) * rstd * g0.w + e0.w);
        h1.x = fmaxf(0.f, (x1.x - mu) * rstd * g1.x + e1.x);
        h1.y = fmaxf(0.f, (x1.y - mu) * rstd * g1.y + e1.y);
        h1.z = fmaxf(0.f, (x1.z - mu) * rstd * g1.z + e1.z);
        h1.w = fmaxf(0.f, (x1.w - mu) * rstd * g1.w + e1.w);

        __syncthreads();
        As[(aCol + 0) * 132 + aRow]      = a0.x;
        As[(aCol + 1) * 132 + aRow]      = a0.y;
        As[(aCol + 2) * 132 + aRow]      = a0.z;
        As[(aCol + 3) * 132 + aRow]      = a0.w;
        As[(aCol + 0) * 132 + aRow + 64] = a1.x;
        As[(aCol + 1) * 132 + aRow + 64] = a1.y;
        As[(aCol + 2) * 132 + aRow + 64] = a1.z;
        As[(aCol + 3) * 132 + aRow + 64] = a1.w;
        *(float4*)(Bs + bRow * 128 + bCol)       = h0;
        *(float4*)(Bs + (bRow + 8) * 128 + bCol) = h1;
        __syncthreads();
        mm16<132, 128>(As, Bs, acc, ty, tx);
    }

#pragma unroll
    for (int i = 0; i < 8; ++i) {
        const int   o  = m0 + ty * 8 + i;
        const float bi = bo[o];
        const size_t off = (size_t)b * D_ * T_ + (size_t)o * T_ + n0 + tx * 8;
        float4 r0 = *(const float4*)(in2 + off);
        float4 r1 = *(const float4*)(in2 + off + 4);
        r0.x += acc[i][0] + bi; r0.y += acc[i][1] + bi;
        r0.z += acc[i][2] + bi; r0.w += acc[i][3] + bi;
        r1.x += acc[i][4] + bi; r1.y += acc[i][5] + bi;
        r1.z += acc[i][6] + bi; r1.w += acc[i][7] + bi;
        *(float4*)(Out + off)     = r0;
        *(float4*)(Out + off + 4) = r1;
    }
}

// ---------------------------------------------------------------------------
// Launcher
// ---------------------------------------------------------------------------
extern "C" void kernel_launch(void* const* d_in, const int* in_sizes, int n_in,
                              void* d_out, int out_size)
{
    const float* input1   = (const float*)d_in[0];
    const float* input2   = (const float*)d_in[1];
    const float* theta_w  = (const float*)d_in[2];
    const float* theta_b  = (const float*)d_in[3];
    const float* phi_w    = (const float*)d_in[4];
    const float* phi_b    = (const float*)d_in[5];
    const float* g_w      = (const float*)d_in[6];
    const float* g_b      = (const float*)d_in[7];
    const float* ln_gamma = (const float*)d_in[8];
    const float* ln_beta  = (const float*)d_in[9];
    const float* out_w    = (const float*)d_in[10];
    const float* out_b    = (const float*)d_in[11];
    float* out = (float*)d_out;

    dim3 blk(256);

    // K1: three projections
    proj_kernel<<<dim3(T_ / 128, L_ / 128, B_), blk>>>(theta_w, theta_b, input2, 0);
    proj_kernel<<<dim3(T_ / 128, L_ / 128, B_), blk>>>(phi_w,   phi_b,   input1, 1);
    proj_kernel<<<dim3(T_ / 128, L_ / 128, B_), blk>>>(g_w,     g_b,     input1, 2);

    // K2: scores
    scores_kernel<<<dim3(T_ / 128, T_ / 128, B_), blk>>>();

    // K3: softmax
    softmax_kernel<<<dim3(B_ * T_), blk>>>();

    // K4: attention apply (t_x -> g_theta)
    attn_kernel<<<dim3(T_ / 128, L_ / 128, B_), blk>>>();

    // K5: LayerNorm stats
    reduce1_kernel<<<dim3(64, B_), blk>>>();
    reduce2_kernel<<<dim3(B_), dim3(64)>>>();

    // K6: fused LN + ReLU + output GEMM + bias + residual
    out_kernel<<<dim3(T_ / 128, D_ / 128, B_), blk>>>(out_w, out_b, ln_gamma,
                                                      ln_beta, input2, out);
}